// round 5
// baseline (speedup 1.0000x reference)
#include <cuda_runtime.h>
#include <math.h>

#define BSZ  4
#define TLEN 4096
#define CDIM 1024
#define HDIM 64
#define MTOT (BSZ * TLEN)
#define NSPLIT 2

// Projected operands. Q and K stored TRANSPOSED [h][m]; Q pre-scaled by H^-0.5.
__device__ float g_Qt[HDIM * MTOT];
__device__ float g_Kt[HDIM * MTOT];
__device__ float g_V [MTOT * HDIM];
// Split-KV partials: unnormalized O and (m, l) stats per split.
__device__ float  g_Opart[NSPLIT * MTOT * HDIM];
__device__ float2 g_stats[NSPLIT * MTOT];

typedef unsigned long long u64;

__device__ __forceinline__ u64 splat2(float x) {
    u64 r; asm("mov.b64 %0, {%1, %1};" : "=l"(r) : "f"(x)); return r;
}
__device__ __forceinline__ u64 pack2(float x, float y) {
    u64 r; asm("mov.b64 %0, {%1, %2};" : "=l"(r) : "f"(x), "f"(y)); return r;
}
__device__ __forceinline__ float2 unpack2(u64 v) {
    float2 f; asm("mov.b64 {%0, %1}, %2;" : "=f"(f.x), "=f"(f.y) : "l"(v)); return f;
}
__device__ __forceinline__ void ffma2(u64 &d, u64 a, u64 b) {
    asm("fma.rn.f32x2 %0, %1, %2, %0;" : "+l"(d) : "l"(a), "l"(b));
}
__device__ __forceinline__ u64 mul2(u64 a, u64 b) {
    u64 r; asm("mul.rn.f32x2 %0, %1, %2;" : "=l"(r) : "l"(a), "l"(b)); return r;
}

// ---------------------------------------------------------------------------
// Projection (unchanged; at fp32 roofline). out[m,h] = sum_c x[m,c]*W[h,c].
// ---------------------------------------------------------------------------
__global__ __launch_bounds__(256) void proj_kernel(
    const float* __restrict__ x,
    const float* __restrict__ Wk,
    const float* __restrict__ Wq,
    const float* __restrict__ Wv)
{
    __shared__ float Xt[32 * 128];
    __shared__ float Wt[32 * 68];

    const int which = blockIdx.y;
    const float* __restrict__ W = (which == 0) ? Wq : (which == 1) ? Wk : Wv;

    const int m0  = blockIdx.x * 128;
    const int tid = threadIdx.x;
    const int r0  = (tid >> 4) * 8;
    const int c0  = (tid & 15) * 4;
    const int rg  = r0 >> 2;

    u64 acc2[4][4];
#pragma unroll
    for (int u = 0; u < 4; u++)
#pragma unroll
        for (int j = 0; j < 4; j++) acc2[u][j] = 0ull;

    for (int kc = 0; kc < CDIM; kc += 32) {
#pragma unroll
        for (int l = 0; l < 4; l++) {
            int idx = tid + l * 256;
            int row = idx >> 3;
            int p   = idx & 7;
            float4 v = *(const float4*)(x + (size_t)(m0 + row) * CDIM + kc + p * 4);
            int mg = row >> 2, ml = row & 3;
            int cc = p * 4;
            Xt[(cc + 0) * 128 + ((mg ^ (cc + 0)) << 2) + ml] = v.x;
            Xt[(cc + 1) * 128 + ((mg ^ (cc + 1)) << 2) + ml] = v.y;
            Xt[(cc + 2) * 128 + ((mg ^ (cc + 2)) << 2) + ml] = v.z;
            Xt[(cc + 3) * 128 + ((mg ^ (cc + 3)) << 2) + ml] = v.w;
        }
#pragma unroll
        for (int l = 0; l < 2; l++) {
            int idx = tid + l * 256;
            int row = idx >> 3;
            int p   = idx & 7;
            float4 v = *(const float4*)(W + (size_t)row * CDIM + kc + p * 4);
            Wt[(p * 4 + 0) * 68 + row] = v.x;
            Wt[(p * 4 + 1) * 68 + row] = v.y;
            Wt[(p * 4 + 2) * 68 + row] = v.z;
            Wt[(p * 4 + 3) * 68 + row] = v.w;
        }
        __syncthreads();

#pragma unroll 8
        for (int k = 0; k < 32; k++) {
            ulonglong2 A0 = *(const ulonglong2*)&Xt[k * 128 + ((rg ^ k) << 2)];
            ulonglong2 A1 = *(const ulonglong2*)&Xt[k * 128 + (((rg + 1) ^ k) << 2)];
            float4 bf = *(const float4*)&Wt[k * 68 + c0];
            u64 b0 = splat2(bf.x), b1 = splat2(bf.y), b2 = splat2(bf.z), b3 = splat2(bf.w);
            ffma2(acc2[0][0], A0.x, b0); ffma2(acc2[0][1], A0.x, b1);
            ffma2(acc2[0][2], A0.x, b2); ffma2(acc2[0][3], A0.x, b3);
            ffma2(acc2[1][0], A0.y, b0); ffma2(acc2[1][1], A0.y, b1);
            ffma2(acc2[1][2], A0.y, b2); ffma2(acc2[1][3], A0.y, b3);
            ffma2(acc2[2][0], A1.x, b0); ffma2(acc2[2][1], A1.x, b1);
            ffma2(acc2[2][2], A1.x, b2); ffma2(acc2[2][3], A1.x, b3);
            ffma2(acc2[3][0], A1.y, b0); ffma2(acc2[3][1], A1.y, b1);
            ffma2(acc2[3][2], A1.y, b2); ffma2(acc2[3][3], A1.y, b3);
        }
        __syncthreads();
    }

    float acc[8][4];
#pragma unroll
    for (int u = 0; u < 4; u++)
#pragma unroll
        for (int j = 0; j < 4; j++) {
            float2 f = unpack2(acc2[u][j]);
            acc[2 * u + 0][j] = f.x;
            acc[2 * u + 1][j] = f.y;
        }

    if (which == 0) {
#pragma unroll
        for (int i = 0; i < 8; i++)
#pragma unroll
            for (int j = 0; j < 4; j++) acc[i][j] *= 0.125f;
    }

    if (which <= 1) {
        float* outT = (which == 0) ? g_Qt : g_Kt;
#pragma unroll
        for (int j = 0; j < 4; j++) {
            float4 lo = make_float4(acc[0][j], acc[1][j], acc[2][j], acc[3][j]);
            float4 hi = make_float4(acc[4][j], acc[5][j], acc[6][j], acc[7][j]);
            *(float4*)&outT[(size_t)(c0 + j) * MTOT + m0 + r0]     = lo;
            *(float4*)&outT[(size_t)(c0 + j) * MTOT + m0 + r0 + 4] = hi;
        }
    } else {
#pragma unroll
        for (int i = 0; i < 8; i++)
            *(float4*)&g_V[(size_t)(m0 + r0 + i) * HDIM + c0] =
                make_float4(acc[i][0], acc[i][1], acc[i][2], acc[i][3]);
    }
}

// ---------------------------------------------------------------------------
// Causal flash attention, split-KV. BM=BN=64, 256 threads, 4x4 tile/thread.
// grid.x = 64*NSPLIT (qb reversed: longest first), grid.y = B.
// Writes unnormalized partial O + (m, l) stats per split; merged afterwards.
// ---------------------------------------------------------------------------
__global__ __launch_bounds__(256, 3) void attn_kernel()
{
    extern __shared__ float sm[];
    float* Qt = sm;                 // [h][row]   64 x 68
    float* Kt = Qt + 64 * 68;       // [h][key]   64 x 68
    float* Vs = Kt + 64 * 68;       // [key][h]   64 x 68
    float* Pt = Vs + 64 * 68;       // [key][row] 64 x 64, swizzled

    const int b     = blockIdx.y;
    const int qb    = 63 - (blockIdx.x >> 1);   // longest CTAs first
    const int split = blockIdx.x & 1;
    const int nblk  = qb + 1;
    const int j0    = (nblk * split) >> 1;
    const int j1    = (nblk * (split + 1)) >> 1;

    const int tid = threadIdx.x;
    const int rg  = tid >> 4;        // 16 row-groups
    const int cg  = tid & 15;        // 16 col-groups
    const int r0  = rg * 4;
    const int c0  = cg * 4;
    const int m0  = b * TLEN + qb * 64;

    float* Op = g_Opart + (size_t)split * MTOT * HDIM;

    if (j0 == j1) {   // empty split: neutral partials
        float4 z = make_float4(0.f, 0.f, 0.f, 0.f);
#pragma unroll
        for (int i = 0; i < 4; i++)
            *(float4*)&Op[(size_t)(m0 + r0 + i) * HDIM + c0] = z;
        if (cg == 0)
#pragma unroll
            for (int i = 0; i < 4; i++)
                g_stats[split * MTOT + m0 + r0 + i] = make_float2(-1e30f, 0.f);
        return;
    }

    // Q tile (pre-scaled): [h][row]
#pragma unroll
    for (int l = 0; l < 4; l++) {
        int idx = tid + l * 256;
        int h = idx >> 4, p = idx & 15;
        *(float4*)&Qt[h * 68 + p * 4] = *(const float4*)&g_Qt[(size_t)h * MTOT + m0 + p * 4];
    }

    u64 o2[2][4];
    float mrow[4], lrow[4];
#pragma unroll
    for (int u = 0; u < 2; u++)
#pragma unroll
        for (int j = 0; j < 4; j++) o2[u][j] = 0ull;
#pragma unroll
    for (int i = 0; i < 4; i++) { mrow[i] = -1e30f; lrow[i] = 0.0f; }

    for (int jb = j0; jb < j1; jb++) {
        const int kb = b * TLEN + jb * 64;
#pragma unroll
        for (int l = 0; l < 4; l++) {
            int idx = tid + l * 256;
            int row = idx >> 4, p = idx & 15;
            *(float4*)&Kt[row * 68 + p * 4] = *(const float4*)&g_Kt[(size_t)row * MTOT + kb + p * 4];
            *(float4*)&Vs[row * 68 + p * 4] = *(const float4*)&g_V[(size_t)(kb + row) * HDIM + p * 4];
        }
        __syncthreads();

        // S = Q^T K (4 rows x 4 keys per thread)
        u64 s2[2][4];
#pragma unroll
        for (int u = 0; u < 2; u++)
#pragma unroll
            for (int j = 0; j < 4; j++) s2[u][j] = 0ull;

#pragma unroll 8
        for (int k = 0; k < 64; k++) {
            ulonglong2 A = *(const ulonglong2*)&Qt[k * 68 + r0];
            float4 bf = *(const float4*)&Kt[k * 68 + c0];
            u64 b0 = splat2(bf.x), b1 = splat2(bf.y), b2 = splat2(bf.z), b3 = splat2(bf.w);
            ffma2(s2[0][0], A.x, b0); ffma2(s2[0][1], A.x, b1);
            ffma2(s2[0][2], A.x, b2); ffma2(s2[0][3], A.x, b3);
            ffma2(s2[1][0], A.y, b0); ffma2(s2[1][1], A.y, b1);
            ffma2(s2[1][2], A.y, b2); ffma2(s2[1][3], A.y, b3);
        }

        float s[4][4];
#pragma unroll
        for (int u = 0; u < 2; u++)
#pragma unroll
            for (int j = 0; j < 4; j++) {
                float2 f = unpack2(s2[u][j]);
                s[2 * u + 0][j] = f.x;
                s[2 * u + 1][j] = f.y;
            }

        if (jb == qb) {
#pragma unroll
            for (int i = 0; i < 4; i++)
#pragma unroll
                for (int j = 0; j < 4; j++)
                    if (c0 + j > r0 + i) s[i][j] = -1e30f;
        }

        // Online softmax (row reductions across 16 lanes)
        float al[4], p[4][4];
#pragma unroll
        for (int i = 0; i < 4; i++) {
            float mloc = fmaxf(fmaxf(s[i][0], s[i][1]), fmaxf(s[i][2], s[i][3]));
#pragma unroll
            for (int d = 1; d < 16; d <<= 1)
                mloc = fmaxf(mloc, __shfl_xor_sync(0xffffffffu, mloc, d));
            float mn = fmaxf(mrow[i], mloc);
            al[i] = __expf(mrow[i] - mn);
            float rs = 0.0f;
#pragma unroll
            for (int j = 0; j < 4; j++) {
                p[i][j] = __expf(s[i][j] - mn);
                rs += p[i][j];
            }
#pragma unroll
            for (int d = 1; d < 16; d <<= 1)
                rs += __shfl_xor_sync(0xffffffffu, rs, d);
            lrow[i] = lrow[i] * al[i] + rs;
            mrow[i] = mn;
        }
#pragma unroll
        for (int u = 0; u < 2; u++) {
            u64 a2 = pack2(al[2 * u], al[2 * u + 1]);
#pragma unroll
            for (int j = 0; j < 4; j++) o2[u][j] = mul2(o2[u][j], a2);
        }

        // Store P transposed, swizzled on key bits [5:2] (distinct banks/lane)
#pragma unroll
        for (int j = 0; j < 4; j++) {
            int key = c0 + j;
            int sw  = (rg ^ (key >> 2)) << 2;
            *(float4*)&Pt[key * 64 + sw] = make_float4(p[0][j], p[1][j], p[2][j], p[3][j]);
        }
        __syncthreads();

        // O += P @ V
#pragma unroll 8
        for (int k = 0; k < 64; k++) {
            ulonglong2 A = *(const ulonglong2*)&Pt[k * 64 + ((rg ^ (k >> 2)) << 2)];
            float4 vf = *(const float4*)&Vs[k * 68 + c0];
            u64 b0 = splat2(vf.x), b1 = splat2(vf.y), b2 = splat2(vf.z), b3 = splat2(vf.w);
            ffma2(o2[0][0], A.x, b0); ffma2(o2[0][1], A.x, b1);
            ffma2(o2[0][2], A.x, b2); ffma2(o2[0][3], A.x, b3);
            ffma2(o2[1][0], A.y, b0); ffma2(o2[1][1], A.y, b1);
            ffma2(o2[1][2], A.y, b2); ffma2(o2[1][3], A.y, b3);
        }
        __syncthreads();
    }

    // Write unnormalized partial O + stats
    float o[4][4];
#pragma unroll
    for (int u = 0; u < 2; u++)
#pragma unroll
        for (int j = 0; j < 4; j++) {
            float2 f = unpack2(o2[u][j]);
            o[2 * u + 0][j] = f.x;
            o[2 * u + 1][j] = f.y;
        }
#pragma unroll
    for (int i = 0; i < 4; i++)
        *(float4*)&Op[(size_t)(m0 + r0 + i) * HDIM + c0] =
            make_float4(o[i][0], o[i][1], o[i][2], o[i][3]);
    if (cg == 0)
#pragma unroll
        for (int i = 0; i < 4; i++)
            g_stats[split * MTOT + m0 + r0 + i] = make_float2(mrow[i], lrow[i]);
}

// ---------------------------------------------------------------------------
// Merge the two split partials. One float4 per thread over [MTOT, H].
// ---------------------------------------------------------------------------
__global__ __launch_bounds__(256) void merge_kernel(float* __restrict__ out)
{
    int idx = blockIdx.x * 256 + threadIdx.x;       // MTOT*16 threads
    int m = idx >> 4;
    int h = (idx & 15) * 4;

    float2 s0 = g_stats[m];
    float2 s1 = g_stats[MTOT + m];
    float mm = fmaxf(s0.x, s1.x);
    float a0 = __expf(s0.x - mm);
    float a1 = __expf(s1.x - mm);
    float rinv = 1.0f / (s0.y * a0 + s1.y * a1);

    float4 o0 = *(const float4*)&g_Opart[(size_t)m * HDIM + h];
    float4 o1 = *(const float4*)&g_Opart[(size_t)(MTOT + m) * HDIM + h];

    float4 r;
    r.x = (o0.x * a0 + o1.x * a1) * rinv;
    r.y = (o0.y * a0 + o1.y * a1) * rinv;
    r.z = (o0.z * a0 + o1.z * a1) * rinv;
    r.w = (o0.w * a0 + o1.w * a1) * rinv;
    *(float4*)&out[(size_t)m * HDIM + h] = r;
}

// ---------------------------------------------------------------------------
extern "C" void kernel_launch(void* const* d_in, const int* in_sizes, int n_in,
                              void* d_out, int out_size)
{
    const float* x  = (const float*)d_in[0];
    const float* Wk = (const float*)d_in[2];
    const float* Wq = (const float*)d_in[3];
    const float* Wv = (const float*)d_in[4];
    float* out = (float*)d_out;

    dim3 gp(128, 3);
    proj_kernel<<<gp, 256>>>(x, Wk, Wq, Wv);

    const int smem_bytes = (3 * 64 * 68 + 64 * 64) * (int)sizeof(float);  // 68608
    cudaFuncSetAttribute(attn_kernel,
                         cudaFuncAttributeMaxDynamicSharedMemorySize, smem_bytes);
    dim3 ga(64 * NSPLIT, 4);
    attn_kernel<<<ga, 256, smem_bytes>>>();

    merge_kernel<<<(MTOT * 16) / 256, 256>>>(out);
}

// round 9
// speedup vs baseline: 1.2877x; 1.2877x over previous
#include <cuda_runtime.h>
#include <cuda_bf16.h>
#include <math.h>
#include <stdint.h>

#define BSZ  4
#define TLEN 4096
#define CDIM 1024
#define HDIM 64
#define MTOT (BSZ * TLEN)
#define NSPLIT 2

// Projected operands. Q and K stored TRANSPOSED [h][m]; Q pre-scaled by H^-0.5.
__device__ float g_Qt[HDIM * MTOT];
__device__ float g_Kt[HDIM * MTOT];
__device__ float g_V [MTOT * HDIM];
// Split-KV partials.
__device__ float  g_Opart[NSPLIT * MTOT * HDIM];
__device__ float2 g_stats[NSPLIT * MTOT];
// Weights pre-split to bf16 hi/lo, [which][h][c], which: 0=Q, 1=K, 2=V.
__device__ __nv_bfloat16 g_Whi[3 * HDIM * CDIM];
__device__ __nv_bfloat16 g_Wlo[3 * HDIM * CDIM];

typedef unsigned long long u64;
typedef unsigned int u32;

// ---------------- f32x2 helpers (attention kernel) ----------------
__device__ __forceinline__ u64 splat2(float x) {
    u64 r; asm("mov.b64 %0, {%1, %1};" : "=l"(r) : "f"(x)); return r;
}
__device__ __forceinline__ u64 pack2(float x, float y) {
    u64 r; asm("mov.b64 %0, {%1, %2};" : "=l"(r) : "f"(x), "f"(y)); return r;
}
__device__ __forceinline__ float2 unpack2(u64 v) {
    float2 f; asm("mov.b64 {%0, %1}, %2;" : "=f"(f.x), "=f"(f.y) : "l"(v)); return f;
}
__device__ __forceinline__ void ffma2(u64 &d, u64 a, u64 b) {
    asm("fma.rn.f32x2 %0, %1, %2, %0;" : "+l"(d) : "l"(a), "l"(b));
}
__device__ __forceinline__ u64 mul2(u64 a, u64 b) {
    u64 r; asm("mul.rn.f32x2 %0, %1, %2;" : "=l"(r) : "l"(a), "l"(b)); return r;
}

// ---------------- mma.sync helpers (sm_80+ path, valid on sm_100 target) ----
__device__ __forceinline__ u32 smem_u32(const void* p) {
    u32 a;
    asm("{ .reg .u64 t; cvta.to.shared.u64 t, %1; cvt.u32.u64 %0, t; }"
        : "=r"(a) : "l"(p));
    return a;
}
__device__ __forceinline__ void ldm_x4(u32 &r0, u32 &r1, u32 &r2, u32 &r3, u32 addr) {
    asm volatile("ldmatrix.sync.aligned.m8n8.x4.shared.b16 {%0,%1,%2,%3}, [%4];"
                 : "=r"(r0), "=r"(r1), "=r"(r2), "=r"(r3) : "r"(addr));
}
__device__ __forceinline__ void ldm_x2(u32 &r0, u32 &r1, u32 addr) {
    asm volatile("ldmatrix.sync.aligned.m8n8.x2.shared.b16 {%0,%1}, [%2];"
                 : "=r"(r0), "=r"(r1) : "r"(addr));
}
__device__ __forceinline__ void mma_bf16(float* d, const u32* a, const u32* b) {
    asm volatile(
        "mma.sync.aligned.m16n8k16.row.col.f32.bf16.bf16.f32 "
        "{%0,%1,%2,%3}, {%4,%5,%6,%7}, {%8,%9}, {%0,%1,%2,%3};"
        : "+f"(d[0]), "+f"(d[1]), "+f"(d[2]), "+f"(d[3])
        : "r"(a[0]), "r"(a[1]), "r"(a[2]), "r"(a[3]), "r"(b[0]), "r"(b[1]));
}

__device__ __forceinline__ u64 pack32(u32 a, u32 b) {
    u64 r; asm("mov.b64 %0, {%1, %2};" : "=l"(r) : "r"(a), "r"(b)); return r;
}
// float4 -> 4 bf16 (hi) + 4 bf16 (lo residual), each packed into a u64
__device__ __forceinline__ void cvt_hilo(float4 v, u64 &hi, u64 &lo) {
    __nv_bfloat162 h01 = __floats2bfloat162_rn(v.x, v.y);
    __nv_bfloat162 h23 = __floats2bfloat162_rn(v.z, v.w);
    float2 f01 = __bfloat1622float2(h01);
    float2 f23 = __bfloat1622float2(h23);
    __nv_bfloat162 l01 = __floats2bfloat162_rn(v.x - f01.x, v.y - f01.y);
    __nv_bfloat162 l23 = __floats2bfloat162_rn(v.z - f23.x, v.w - f23.y);
    hi = pack32(*(u32*)&h01, *(u32*)&h23);
    lo = pack32(*(u32*)&l01, *(u32*)&l23);
}

// ---------------------------------------------------------------------------
// Weight pre-split: fp32 -> bf16 hi/lo. which: 0=Wq, 1=Wk, 2=Wv.
// ---------------------------------------------------------------------------
__global__ __launch_bounds__(256) void wconv_kernel(
    const float* __restrict__ Wk,
    const float* __restrict__ Wq,
    const float* __restrict__ Wv)
{
    int idx = blockIdx.x * 256 + threadIdx.x;     // 3 * 65536
    int w = idx >> 16;
    int r = idx & 0xFFFF;
    const float* src = (w == 0) ? Wq : (w == 1) ? Wk : Wv;
    float v = src[r];
    __nv_bfloat16 hi = __float2bfloat16(v);
    __nv_bfloat16 lo = __float2bfloat16(v - __bfloat162float(hi));
    g_Whi[idx] = hi;
    g_Wlo[idx] = lo;
}

// ---------------------------------------------------------------------------
// Tensor-core projection via mma.sync, bf16x3 split. D = X @ W^T.
// grid (128, 3): blockIdx.y selects Q/K/V. 256 threads = 8 warps.
// CTA tile: BM=128, BN=64, BK=64 (16 chunks). Warp tile 32x32.
// smem bf16 pitch 72 (144B rows, 16B-aligned, ldmatrix conflict-free phases).
// ---------------------------------------------------------------------------
#define PITCH 72
#define A_HI 0
#define A_LO (128 * PITCH * 2)                    // 18432
#define B_HI (2 * 128 * PITCH * 2)                // 36864
#define B_LO (B_HI + 64 * PITCH * 2)              // 46080
#define PROJ_SMEM (B_LO + 64 * PITCH * 2)         // 55296

__global__ __launch_bounds__(256) void proj_tc_kernel(const float* __restrict__ x)
{
    extern __shared__ char psm[];
    const u32 sb = smem_u32(psm);

    const int which = blockIdx.y;
    const int m0    = blockIdx.x * 128;
    const int tid   = threadIdx.x;
    const int wid   = tid >> 5;
    const int lane  = tid & 31;
    const int wm    = (wid & 3) * 32;   // warp m-offset
    const int wn    = (wid >> 2) * 32;  // warp n-offset

    const __nv_bfloat16* Whi = g_Whi + (size_t)which * HDIM * CDIM;
    const __nv_bfloat16* Wlo = g_Wlo + (size_t)which * HDIM * CDIM;

    float acc[2][4][4];
#pragma unroll
    for (int mt = 0; mt < 2; mt++)
#pragma unroll
        for (int nt = 0; nt < 4; nt++)
#pragma unroll
            for (int c = 0; c < 4; c++) acc[mt][nt][c] = 0.0f;

    // Fragment smem addresses (fixed per thread, advance by k-step)
    const int arow = (lane & 15);
    const int acol8 = (lane >> 4) << 3;           // 0 or 8
    const int brow = (lane & 7);
    const int bcol8 = ((lane >> 3) & 1) << 3;     // 0 or 8 (lanes 16+ mirror 0-15)

#pragma unroll 1
    for (int chunk = 0; chunk < 16; chunk++) {
        const int kc = chunk * 64;

        // Load X chunk [128 x 64] f32 -> bf16 hi/lo smem
#pragma unroll
        for (int i = 0; i < 8; i++) {
            int idx = tid + i * 256;
            int row = idx >> 4;
            int cg  = idx & 15;
            float4 v = *(const float4*)(x + (size_t)(m0 + row) * CDIM + kc + cg * 4);
            u64 hi, lo;
            cvt_hilo(v, hi, lo);
            *(u64*)(psm + A_HI + row * (PITCH * 2) + cg * 8) = hi;
            *(u64*)(psm + A_LO + row * (PITCH * 2) + cg * 8) = lo;
        }
        // Load W chunk [64 x 64] bf16 hi+lo: 2 tiles x 1024 u64 items = 2048
#pragma unroll
        for (int i = 0; i < 8; i++) {
            int idx = tid + i * 256;
            int t   = idx >> 10;                  // 0=hi, 1=lo
            int rem = idx & 1023;
            int row = rem >> 4;
            int cg  = rem & 15;
            const __nv_bfloat16* src = t ? Wlo : Whi;
            u64 v = *(const u64*)(src + (size_t)row * CDIM + kc + cg * 4);
            *(u64*)(psm + (t ? B_LO : B_HI) + row * (PITCH * 2) + cg * 8) = v;
        }
        __syncthreads();

#pragma unroll
        for (int ks = 0; ks < 4; ks++) {
            const int kb = ks * 16;
            u32 ah[2][4], al[2][4], bh[4][2], bl[4][2];
#pragma unroll
            for (int mt = 0; mt < 2; mt++) {
                u32 ra = (wm + mt * 16 + arow) * (PITCH * 2) + (kb + acol8) * 2;
                ldm_x4(ah[mt][0], ah[mt][1], ah[mt][2], ah[mt][3], sb + A_HI + ra);
                ldm_x4(al[mt][0], al[mt][1], al[mt][2], al[mt][3], sb + A_LO + ra);
            }
#pragma unroll
            for (int nt = 0; nt < 4; nt++) {
                u32 rb = (wn + nt * 8 + brow) * (PITCH * 2) + (kb + bcol8) * 2;
                ldm_x2(bh[nt][0], bh[nt][1], sb + B_HI + rb);
                ldm_x2(bl[nt][0], bl[nt][1], sb + B_LO + rb);
            }
#pragma unroll
            for (int mt = 0; mt < 2; mt++)
#pragma unroll
                for (int nt = 0; nt < 4; nt++) {
                    mma_bf16(acc[mt][nt], ah[mt], bh[nt]);
                    mma_bf16(acc[mt][nt], ah[mt], bl[nt]);
                    mma_bf16(acc[mt][nt], al[mt], bh[nt]);
                }
        }
        __syncthreads();
    }

    // Epilogue. Fragment c0,c1 -> (row gid, cols 2tig,2tig+1); c2,c3 -> row gid+8.
    const int gid = lane >> 2;
    const int tig = lane & 3;
    const float qscale = (which == 0) ? 0.125f : 1.0f;

#pragma unroll
    for (int mt = 0; mt < 2; mt++)
#pragma unroll
        for (int nt = 0; nt < 4; nt++) {
            int m = m0 + wm + mt * 16 + gid;
            int n = wn + nt * 8 + 2 * tig;
            float v0 = acc[mt][nt][0] * qscale;
            float v1 = acc[mt][nt][1] * qscale;
            float v2 = acc[mt][nt][2] * qscale;
            float v3 = acc[mt][nt][3] * qscale;
            if (which == 2) {
                *(float2*)&g_V[(size_t)m * HDIM + n]       = make_float2(v0, v1);
                *(float2*)&g_V[(size_t)(m + 8) * HDIM + n] = make_float2(v2, v3);
            } else {
                float* outT = (which == 0) ? g_Qt : g_Kt;
                outT[(size_t)n * MTOT + m]           = v0;
                outT[(size_t)(n + 1) * MTOT + m]     = v1;
                outT[(size_t)n * MTOT + m + 8]       = v2;
                outT[(size_t)(n + 1) * MTOT + m + 8] = v3;
            }
        }
}

// ---------------------------------------------------------------------------
// Causal flash attention, split-KV (unchanged from R5 best).
// ---------------------------------------------------------------------------
__global__ __launch_bounds__(256, 3) void attn_kernel()
{
    extern __shared__ float sm[];
    float* Qt = sm;
    float* Kt = Qt + 64 * 68;
    float* Vs = Kt + 64 * 68;
    float* Pt = Vs + 64 * 68;

    const int b     = blockIdx.y;
    const int qb    = 63 - (blockIdx.x >> 1);
    const int split = blockIdx.x & 1;
    const int nblk  = qb + 1;
    const int j0    = (nblk * split) >> 1;
    const int j1    = (nblk * (split + 1)) >> 1;

    const int tid = threadIdx.x;
    const int rg  = tid >> 4;
    const int cg  = tid & 15;
    const int r0  = rg * 4;
    const int c0  = cg * 4;
    const int m0  = b * TLEN + qb * 64;

    float* Op = g_Opart + (size_t)split * MTOT * HDIM;

    if (j0 == j1) {
        float4 z = make_float4(0.f, 0.f, 0.f, 0.f);
#pragma unroll
        for (int i = 0; i < 4; i++)
            *(float4*)&Op[(size_t)(m0 + r0 + i) * HDIM + c0] = z;
        if (cg == 0)
#pragma unroll
            for (int i = 0; i < 4; i++)
                g_stats[split * MTOT + m0 + r0 + i] = make_float2(-1e30f, 0.f);
        return;
    }

#pragma unroll
    for (int l = 0; l < 4; l++) {
        int idx = tid + l * 256;
        int h = idx >> 4, p = idx & 15;
        *(float4*)&Qt[h * 68 + p * 4] = *(const float4*)&g_Qt[(size_t)h * MTOT + m0 + p * 4];
    }

    u64 o2[2][4];
    float mrow[4], lrow[4];
#pragma unroll
    for (int u = 0; u < 2; u++)
#pragma unroll
        for (int j = 0; j < 4; j++) o2[u][j] = 0ull;
#pragma unroll
    for (int i = 0; i < 4; i++) { mrow[i] = -1e30f; lrow[i] = 0.0f; }

    for (int jb = j0; jb < j1; jb++) {
        const int kb = b * TLEN + jb * 64;
#pragma unroll
        for (int l = 0; l < 4; l++) {
            int idx = tid + l * 256;
            int row = idx >> 4, p = idx & 15;
            *(float4*)&Kt[row * 68 + p * 4] = *(const float4*)&g_Kt[(size_t)row * MTOT + kb + p * 4];
            *(float4*)&Vs[row * 68 + p * 4] = *(const float4*)&g_V[(size_t)(kb + row) * HDIM + p * 4];
        }
        __syncthreads();

        u64 s2[2][4];
#pragma unroll
        for (int u = 0; u < 2; u++)
#pragma unroll
            for (int j = 0; j < 4; j++) s2[u][j] = 0ull;

#pragma unroll 8
        for (int k = 0; k < 64; k++) {
            ulonglong2 A = *(const ulonglong2*)&Qt[k * 68 + r0];
            float4 bf = *(const float4*)&Kt[k * 68 + c0];
            u64 b0 = splat2(bf.x), b1 = splat2(bf.y), b2 = splat2(bf.z), b3 = splat2(bf.w);
            ffma2(s2[0][0], A.x, b0); ffma2(s2[0][1], A.x, b1);
            ffma2(s2[0][2], A.x, b2); ffma2(s2[0][3], A.x, b3);
            ffma2(s2[1][0], A.y, b0); ffma2(s2[1][1], A.y, b1);
            ffma2(s2[1][2], A.y, b2); ffma2(s2[1][3], A.y, b3);
        }

        float s[4][4];
#pragma unroll
        for (int u = 0; u < 2; u++)
#pragma unroll
            for (int j = 0; j < 4; j++) {
                float2 f = unpack2(s2[u][j]);
                s[2 * u + 0][j] = f.x;
                s[2 * u + 1][j] = f.y;
            }

        if (jb == qb) {
#pragma unroll
            for (int i = 0; i < 4; i++)
#pragma unroll
                for (int j = 0; j < 4; j++)
                    if (c0 + j > r0 + i) s[i][j] = -1e30f;
        }

        float al[4], p[4][4];
#pragma unroll
        for (int i = 0; i < 4; i++) {
            float mloc = fmaxf(fmaxf(s[i][0], s[i][1]), fmaxf(s[i][2], s[i][3]));
#pragma unroll
            for (int d = 1; d < 16; d <<= 1)
                mloc = fmaxf(mloc, __shfl_xor_sync(0xffffffffu, mloc, d));
            float mn = fmaxf(mrow[i], mloc);
            al[i] = __expf(mrow[i] - mn);
            float rs = 0.0f;
#pragma unroll
            for (int j = 0; j < 4; j++) {
                p[i][j] = __expf(s[i][j] - mn);
                rs += p[i][j];
            }
#pragma unroll
            for (int d = 1; d < 16; d <<= 1)
                rs += __shfl_xor_sync(0xffffffffu, rs, d);
            lrow[i] = lrow[i] * al[i] + rs;
            mrow[i] = mn;
        }
#pragma unroll
        for (int u = 0; u < 2; u++) {
            u64 a2 = pack2(al[2 * u], al[2 * u + 1]);
#pragma unroll
            for (int j = 0; j < 4; j++) o2[u][j] = mul2(o2[u][j], a2);
        }

#pragma unroll
        for (int j = 0; j < 4; j++) {
            int key = c0 + j;
            int sw  = (rg ^ (key >> 2)) << 2;
            *(float4*)&Pt[key * 64 + sw] = make_float4(p[0][j], p[1][j], p[2][j], p[3][j]);
        }
        __syncthreads();

#pragma unroll 8
        for (int k = 0; k < 64; k++) {
            ulonglong2 A = *(const ulonglong2*)&Pt[k * 64 + ((rg ^ (k >> 2)) << 2)];
            float4 vf = *(const float4*)&Vs[k * 68 + c0];
            u64 b0 = splat2(vf.x), b1 = splat2(vf.y), b2 = splat2(vf.z), b3 = splat2(vf.w);
            ffma2(o2[0][0], A.x, b0); ffma2(o2[0][1], A.x, b1);
            ffma2(o2[0][2], A.x, b2); ffma2(o2[0][3], A.x, b3);
            ffma2(o2[1][0], A.y, b0); ffma2(o2[1][1], A.y, b1);
            ffma2(o2[1][2], A.y, b2); ffma2(o2[1][3], A.y, b3);
        }
        __syncthreads();
    }

    float o[4][4];
#pragma unroll
    for (int u = 0; u < 2; u++)
#pragma unroll
        for (int j = 0; j < 4; j++) {
            float2 f = unpack2(o2[u][j]);
            o[2 * u + 0][j] = f.x;
            o[2 * u + 1][j] = f.y;
        }
#pragma unroll
    for (int i = 0; i < 4; i++)
        *(float4*)&Op[(size_t)(m0 + r0 + i) * HDIM + c0] =
            make_float4(o[i][0], o[i][1], o[i][2], o[i][3]);
    if (cg == 0)
#pragma unroll
        for (int i = 0; i < 4; i++)
            g_stats[split * MTOT + m0 + r0 + i] = make_float2(mrow[i], lrow[i]);
}

// ---------------------------------------------------------------------------
__global__ __launch_bounds__(256) void merge_kernel(float* __restrict__ out)
{
    int idx = blockIdx.x * 256 + threadIdx.x;
    int m = idx >> 4;
    int h = (idx & 15) * 4;

    float2 s0 = g_stats[m];
    float2 s1 = g_stats[MTOT + m];
    float mm = fmaxf(s0.x, s1.x);
    float a0 = __expf(s0.x - mm);
    float a1 = __expf(s1.x - mm);
    float rinv = 1.0f / (s0.y * a0 + s1.y * a1);

    float4 o0 = *(const float4*)&g_Opart[(size_t)m * HDIM + h];
    float4 o1 = *(const float4*)&g_Opart[(size_t)(MTOT + m) * HDIM + h];

    float4 r;
    r.x = (o0.x * a0 + o1.x * a1) * rinv;
    r.y = (o0.y * a0 + o1.y * a1) * rinv;
    r.z = (o0.z * a0 + o1.z * a1) * rinv;
    r.w = (o0.w * a0 + o1.w * a1) * rinv;
    *(float4*)&out[(size_t)m * HDIM + h] = r;
}

// ---------------------------------------------------------------------------
extern "C" void kernel_launch(void* const* d_in, const int* in_sizes, int n_in,
                              void* d_out, int out_size)
{
    const float* x  = (const float*)d_in[0];
    const float* Wk = (const float*)d_in[2];
    const float* Wq = (const float*)d_in[3];
    const float* Wv = (const float*)d_in[4];
    float* out = (float*)d_out;

    wconv_kernel<<<3 * HDIM * CDIM / 256, 256>>>(Wk, Wq, Wv);

    cudaFuncSetAttribute(proj_tc_kernel,
                         cudaFuncAttributeMaxDynamicSharedMemorySize, PROJ_SMEM);
    dim3 gp(128, 3);
    proj_tc_kernel<<<gp, 256, PROJ_SMEM>>>(x);

    const int smem_bytes = (3 * 64 * 68 + 64 * 64) * (int)sizeof(float);
    cudaFuncSetAttribute(attn_kernel,
                         cudaFuncAttributeMaxDynamicSharedMemorySize, smem_bytes);
    dim3 ga(64 * NSPLIT, 4);
    attn_kernel<<<ga, 256, smem_bytes>>>();

    merge_kernel<<<(MTOT * 16) / 256, 256>>>(out);
}

// round 11
// speedup vs baseline: 2.2875x; 1.7764x over previous
#include <cuda_runtime.h>
#include <cuda_bf16.h>
#include <math.h>
#include <stdint.h>

#define BSZ  4
#define TLEN 4096
#define CDIM 1024
#define HDIM 64
#define MTOT (BSZ * TLEN)
#define NSPLIT 2

// Projected operands, bf16 hi/lo split.
// Q (pre-scaled by 0.125*log2(e)) and K: [m][h] row-major. Vt: [h][m] (transposed).
__device__ __nv_bfloat16 g_Qhi[MTOT * HDIM], g_Qlo[MTOT * HDIM];
__device__ __nv_bfloat16 g_Khi[MTOT * HDIM], g_Klo[MTOT * HDIM];
__device__ __nv_bfloat16 g_Vthi[HDIM * MTOT], g_Vtlo[HDIM * MTOT];
// Split-KV partials.
__device__ float  g_Opart[NSPLIT * MTOT * HDIM];
__device__ float2 g_stats[NSPLIT * MTOT];
// Weights pre-split to bf16 hi/lo, [which][h][c], which: 0=Q, 1=K, 2=V.
__device__ __nv_bfloat16 g_Whi[3 * HDIM * CDIM];
__device__ __nv_bfloat16 g_Wlo[3 * HDIM * CDIM];

typedef unsigned long long u64;
typedef unsigned int u32;

// ---------------- mma.sync helpers ----------------
__device__ __forceinline__ u32 smem_u32(const void* p) {
    u32 a;
    asm("{ .reg .u64 t; cvta.to.shared.u64 t, %1; cvt.u32.u64 %0, t; }"
        : "=r"(a) : "l"(p));
    return a;
}
__device__ __forceinline__ void ldm_x4(u32 &r0, u32 &r1, u32 &r2, u32 &r3, u32 addr) {
    asm volatile("ldmatrix.sync.aligned.m8n8.x4.shared.b16 {%0,%1,%2,%3}, [%4];"
                 : "=r"(r0), "=r"(r1), "=r"(r2), "=r"(r3) : "r"(addr));
}
__device__ __forceinline__ void ldm_x2(u32 &r0, u32 &r1, u32 addr) {
    asm volatile("ldmatrix.sync.aligned.m8n8.x2.shared.b16 {%0,%1}, [%2];"
                 : "=r"(r0), "=r"(r1) : "r"(addr));
}
__device__ __forceinline__ void mma_bf16(float* d, const u32* a, const u32* b) {
    asm volatile(
        "mma.sync.aligned.m16n8k16.row.col.f32.bf16.bf16.f32 "
        "{%0,%1,%2,%3}, {%4,%5,%6,%7}, {%8,%9}, {%0,%1,%2,%3};"
        : "+f"(d[0]), "+f"(d[1]), "+f"(d[2]), "+f"(d[3])
        : "r"(a[0]), "r"(a[1]), "r"(a[2]), "r"(a[3]), "r"(b[0]), "r"(b[1]));
}
__device__ __forceinline__ u64 pack32(u32 a, u32 b) {
    u64 r; asm("mov.b64 %0, {%1, %2};" : "=l"(r) : "r"(a), "r"(b)); return r;
}
__device__ __forceinline__ u32 cvt_bf2(float a, float b) {
    __nv_bfloat162 h = __floats2bfloat162_rn(a, b);
    return *(u32*)&h;
}
__device__ __forceinline__ float2 bf2_to_f2(u32 v) {
    __nv_bfloat162 h = *(__nv_bfloat162*)&v;
    return __bfloat1622float2(h);
}
// float4 -> 4 bf16 hi + 4 bf16 lo, packed u64s (for X conversion in proj)
__device__ __forceinline__ void cvt_hilo(float4 v, u64 &hi, u64 &lo) {
    u32 h01 = cvt_bf2(v.x, v.y), h23 = cvt_bf2(v.z, v.w);
    float2 f01 = bf2_to_f2(h01), f23 = bf2_to_f2(h23);
    u32 l01 = cvt_bf2(v.x - f01.x, v.y - f01.y);
    u32 l23 = cvt_bf2(v.z - f23.x, v.w - f23.y);
    hi = pack32(h01, h23);
    lo = pack32(l01, l23);
}

// ---------------------------------------------------------------------------
// Weight pre-split: fp32 -> bf16 hi/lo. which: 0=Wq, 1=Wk, 2=Wv.
// ---------------------------------------------------------------------------
__global__ __launch_bounds__(256) void wconv_kernel(
    const float* __restrict__ Wk,
    const float* __restrict__ Wq,
    const float* __restrict__ Wv)
{
    int idx = blockIdx.x * 256 + threadIdx.x;     // 3 * 65536
    int w = idx >> 16;
    int r = idx & 0xFFFF;
    const float* src = (w == 0) ? Wq : (w == 1) ? Wk : Wv;
    float v = src[r];
    __nv_bfloat16 hi = __float2bfloat16(v);
    __nv_bfloat16 lo = __float2bfloat16(v - __bfloat162float(hi));
    g_Whi[idx] = hi;
    g_Wlo[idx] = lo;
}

// ---------------------------------------------------------------------------
// Tensor-core projection via mma.sync, bf16x3 split (proven R9 mainloop).
// Epilogue emits bf16 hi/lo operand arrays for the attention kernel.
// ---------------------------------------------------------------------------
#define PITCH 72
#define A_HI 0
#define A_LO (128 * PITCH * 2)                    // 18432
#define B_HI (2 * 128 * PITCH * 2)                // 36864
#define B_LO (B_HI + 64 * PITCH * 2)              // 46080
#define PROJ_SMEM (B_LO + 64 * PITCH * 2)         // 55296

__global__ __launch_bounds__(256) void proj_tc_kernel(const float* __restrict__ x)
{
    extern __shared__ char psm[];
    const u32 sb = smem_u32(psm);

    const int which = blockIdx.y;
    const int m0    = blockIdx.x * 128;
    const int tid   = threadIdx.x;
    const int wid   = tid >> 5;
    const int lane  = tid & 31;
    const int wm    = (wid & 3) * 32;
    const int wn    = (wid >> 2) * 32;

    const __nv_bfloat16* Whi = g_Whi + (size_t)which * HDIM * CDIM;
    const __nv_bfloat16* Wlo = g_Wlo + (size_t)which * HDIM * CDIM;

    float acc[2][4][4];
#pragma unroll
    for (int mt = 0; mt < 2; mt++)
#pragma unroll
        for (int nt = 0; nt < 4; nt++)
#pragma unroll
            for (int c = 0; c < 4; c++) acc[mt][nt][c] = 0.0f;

    const int arow = (lane & 15);
    const int acol8 = (lane >> 4) << 3;
    const int brow = (lane & 7);
    const int bcol8 = ((lane >> 3) & 1) << 3;

#pragma unroll 1
    for (int chunk = 0; chunk < 16; chunk++) {
        const int kc = chunk * 64;

#pragma unroll
        for (int i = 0; i < 8; i++) {
            int idx = tid + i * 256;
            int row = idx >> 4;
            int cg  = idx & 15;
            float4 v = *(const float4*)(x + (size_t)(m0 + row) * CDIM + kc + cg * 4);
            u64 hi, lo;
            cvt_hilo(v, hi, lo);
            *(u64*)(psm + A_HI + row * (PITCH * 2) + cg * 8) = hi;
            *(u64*)(psm + A_LO + row * (PITCH * 2) + cg * 8) = lo;
        }
#pragma unroll
        for (int i = 0; i < 8; i++) {
            int idx = tid + i * 256;
            int t   = idx >> 10;
            int rem = idx & 1023;
            int row = rem >> 4;
            int cg  = rem & 15;
            const __nv_bfloat16* src = t ? Wlo : Whi;
            u64 v = *(const u64*)(src + (size_t)row * CDIM + kc + cg * 4);
            *(u64*)(psm + (t ? B_LO : B_HI) + row * (PITCH * 2) + cg * 8) = v;
        }
        __syncthreads();

#pragma unroll
        for (int ks = 0; ks < 4; ks++) {
            const int kb = ks * 16;
            u32 ah[2][4], al[2][4], bh[4][2], bl[4][2];
#pragma unroll
            for (int mt = 0; mt < 2; mt++) {
                u32 ra = (wm + mt * 16 + arow) * (PITCH * 2) + (kb + acol8) * 2;
                ldm_x4(ah[mt][0], ah[mt][1], ah[mt][2], ah[mt][3], sb + A_HI + ra);
                ldm_x4(al[mt][0], al[mt][1], al[mt][2], al[mt][3], sb + A_LO + ra);
            }
#pragma unroll
            for (int nt = 0; nt < 4; nt++) {
                u32 rb = (wn + nt * 8 + brow) * (PITCH * 2) + (kb + bcol8) * 2;
                ldm_x2(bh[nt][0], bh[nt][1], sb + B_HI + rb);
                ldm_x2(bl[nt][0], bl[nt][1], sb + B_LO + rb);
            }
#pragma unroll
            for (int mt = 0; mt < 2; mt++)
#pragma unroll
                for (int nt = 0; nt < 4; nt++) {
                    mma_bf16(acc[mt][nt], ah[mt], bh[nt]);
                    mma_bf16(acc[mt][nt], ah[mt], bl[nt]);
                    mma_bf16(acc[mt][nt], al[mt], bh[nt]);
                }
        }
        __syncthreads();
    }

    // Epilogue -> bf16 hi/lo operand arrays.
    const int gid = lane >> 2;
    const int tig = lane & 3;
    // Q pre-scaled by H^-0.5 * log2(e) so attention softmax uses exp2.
    const float qsc = 0.18033688011112042f;

#pragma unroll
    for (int mt = 0; mt < 2; mt++)
#pragma unroll
        for (int nt = 0; nt < 4; nt++) {
            int m = m0 + wm + mt * 16 + gid;
            int n = wn + nt * 8 + 2 * tig;
            float sc = (which == 0) ? qsc : 1.0f;
            float v0 = acc[mt][nt][0] * sc;
            float v1 = acc[mt][nt][1] * sc;
            float v2 = acc[mt][nt][2] * sc;
            float v3 = acc[mt][nt][3] * sc;

            if (which == 2) {
                // Vt [h][m]: transposed scalar bf16 stores
                __nv_bfloat16 h0 = __float2bfloat16(v0);
                __nv_bfloat16 h1 = __float2bfloat16(v1);
                __nv_bfloat16 h2 = __float2bfloat16(v2);
                __nv_bfloat16 h3 = __float2bfloat16(v3);
                g_Vthi[(size_t)n * MTOT + m]           = h0;
                g_Vthi[(size_t)(n + 1) * MTOT + m]     = h1;
                g_Vthi[(size_t)n * MTOT + m + 8]       = h2;
                g_Vthi[(size_t)(n + 1) * MTOT + m + 8] = h3;
                g_Vtlo[(size_t)n * MTOT + m]           = __float2bfloat16(v0 - __bfloat162float(h0));
                g_Vtlo[(size_t)(n + 1) * MTOT + m]     = __float2bfloat16(v1 - __bfloat162float(h1));
                g_Vtlo[(size_t)n * MTOT + m + 8]       = __float2bfloat16(v2 - __bfloat162float(h2));
                g_Vtlo[(size_t)(n + 1) * MTOT + m + 8] = __float2bfloat16(v3 - __bfloat162float(h3));
            } else {
                __nv_bfloat16* Ahi = (which == 0) ? g_Qhi : g_Khi;
                __nv_bfloat16* Alo = (which == 0) ? g_Qlo : g_Klo;
                u32 h01 = cvt_bf2(v0, v1);
                float2 f01 = bf2_to_f2(h01);
                u32 l01 = cvt_bf2(v0 - f01.x, v1 - f01.y);
                u32 h23 = cvt_bf2(v2, v3);
                float2 f23 = bf2_to_f2(h23);
                u32 l23 = cvt_bf2(v2 - f23.x, v3 - f23.y);
                *(u32*)&Ahi[(size_t)m * HDIM + n]       = h01;
                *(u32*)&Alo[(size_t)m * HDIM + n]       = l01;
                *(u32*)&Ahi[(size_t)(m + 8) * HDIM + n] = h23;
                *(u32*)&Alo[(size_t)(m + 8) * HDIM + n] = l23;
            }
        }
}

// ---------------------------------------------------------------------------
// FA2-style tensor-core causal flash attention, split-KV.
// BM=64 q-rows per CTA, 128 threads (4 warps x 16-row strips), BN=64 keys.
// hi/lo bf16 3-product for both S=QK^T and O=PV. P repacked C-frag -> A-frag
// in registers (no P smem). Softmax in log2 domain (Q pre-scaled).
// grid = (64*NSPLIT, B); writes unnormalized partials + (m,l) stats.
// ---------------------------------------------------------------------------
#define QH_OFF 0
#define QL_OFF 9216
#define KH_OFF 18432
#define KL_OFF 27648
#define VH_OFF 36864
#define VL_OFF 46080
#define ATTN_SMEM 55296

__global__ __launch_bounds__(128) void attn_tc_kernel()
{
    extern __shared__ char csm[];
    const u32 sb = smem_u32(csm);

    const int b     = blockIdx.y;
    const int qb    = 63 - (blockIdx.x >> 1);   // longest CTAs first
    const int split = blockIdx.x & 1;
    const int nblk  = qb + 1;
    const int j0    = (nblk * split) >> 1;
    const int j1    = (nblk * (split + 1)) >> 1;

    const int tid  = threadIdx.x;
    const int wid  = tid >> 5;
    const int lane = tid & 31;
    const int gid  = lane >> 2;
    const int tig  = lane & 3;
    const int wm   = wid * 16;
    const int m0   = b * TLEN + qb * 64;

    float* Op = g_Opart + (size_t)split * MTOT * HDIM;

    if (j0 == j1) {   // empty split: neutral partials
#pragma unroll
        for (int nt = 0; nt < 8; nt++) {
            int n = nt * 8 + 2 * tig;
            *(float2*)&Op[(size_t)(m0 + wm + gid) * HDIM + n]     = make_float2(0.f, 0.f);
            *(float2*)&Op[(size_t)(m0 + wm + gid + 8) * HDIM + n] = make_float2(0.f, 0.f);
        }
        if (tig == 0) {
            g_stats[split * MTOT + m0 + wm + gid]     = make_float2(-1e30f, 0.f);
            g_stats[split * MTOT + m0 + wm + gid + 8] = make_float2(-1e30f, 0.f);
        }
        return;
    }

    // ---- Load Q tile (64 x 64 bf16 hi/lo) into smem, then to A-fragments ----
#pragma unroll
    for (int i = 0; i < 16; i++) {
        int idx  = tid + i * 128;       // 0..2047
        int half = idx >> 10;
        int rem  = idx & 1023;
        int row  = rem >> 4;
        int cg   = rem & 15;
        const __nv_bfloat16* src = half ? g_Qlo : g_Qhi;
        u64 v = *(const u64*)(src + (size_t)(m0 + row) * HDIM + cg * 4);
        *(u64*)(csm + (half ? QL_OFF : QH_OFF) + row * (PITCH * 2) + cg * 8) = v;
    }
    __syncthreads();

    const int arow  = (lane & 15);
    const int acol8 = (lane >> 4) << 3;
    const int brow  = (lane & 7);
    const int bcol8 = ((lane >> 3) & 1) << 3;

    u32 qh[4][4], ql[4][4];
#pragma unroll
    for (int kk = 0; kk < 4; kk++) {
        u32 ra = (wm + arow) * (PITCH * 2) + (kk * 16 + acol8) * 2;
        ldm_x4(qh[kk][0], qh[kk][1], qh[kk][2], qh[kk][3], sb + QH_OFF + ra);
        ldm_x4(ql[kk][0], ql[kk][1], ql[kk][2], ql[kk][3], sb + QL_OFF + ra);
    }

    float o[8][4];
#pragma unroll
    for (int nt = 0; nt < 8; nt++)
#pragma unroll
        for (int c = 0; c < 4; c++) o[nt][c] = 0.0f;
    float mrow0 = -1e30f, mrow1 = -1e30f, lrow0 = 0.0f, lrow1 = 0.0f;

    for (int jb = j0; jb < j1; jb++) {
        const int kb = b * TLEN + jb * 64;

        // Load K [key][h] and Vt [h][key] hi/lo tiles
#pragma unroll
        for (int i = 0; i < 16; i++) {
            int idx  = tid + i * 128;
            int half = idx >> 10;
            int rem  = idx & 1023;
            int row  = rem >> 4;
            int cg   = rem & 15;
            const __nv_bfloat16* src = half ? g_Klo : g_Khi;
            u64 v = *(const u64*)(src + (size_t)(kb + row) * HDIM + cg * 4);
            *(u64*)(csm + (half ? KL_OFF : KH_OFF) + row * (PITCH * 2) + cg * 8) = v;
        }
#pragma unroll
        for (int i = 0; i < 16; i++) {
            int idx  = tid + i * 128;
            int half = idx >> 10;
            int rem  = idx & 1023;
            int row  = rem >> 4;      // h
            int cg   = rem & 15;      // key chunk
            const __nv_bfloat16* src = half ? g_Vtlo : g_Vthi;
            u64 v = *(const u64*)(src + (size_t)row * MTOT + kb + cg * 4);
            *(u64*)(csm + (half ? VL_OFF : VH_OFF) + row * (PITCH * 2) + cg * 8) = v;
        }
        __syncthreads();

        // ---- S = Q K^T (log2 domain), 16 x 64 per warp ----
        float s[8][4];
#pragma unroll
        for (int nt = 0; nt < 8; nt++)
#pragma unroll
            for (int c = 0; c < 4; c++) s[nt][c] = 0.0f;

#pragma unroll
        for (int kk = 0; kk < 4; kk++) {
#pragma unroll
            for (int nt = 0; nt < 8; nt++) {
                u32 bh[2], bl[2];
                u32 rb = (nt * 8 + brow) * (PITCH * 2) + (kk * 16 + bcol8) * 2;
                ldm_x2(bh[0], bh[1], sb + KH_OFF + rb);
                ldm_x2(bl[0], bl[1], sb + KL_OFF + rb);
                mma_bf16(s[nt], qh[kk], bh);
                mma_bf16(s[nt], qh[kk], bl);
                mma_bf16(s[nt], ql[kk], bh);
            }
        }

        // ---- Causal mask (diagonal block only) ----
        if (jb == qb) {
#pragma unroll
            for (int nt = 0; nt < 8; nt++) {
                int col = nt * 8 + 2 * tig;
                int rA = wm + gid, rB = wm + gid + 8;
                if (col > rA)     s[nt][0] = -1e30f;
                if (col + 1 > rA) s[nt][1] = -1e30f;
                if (col > rB)     s[nt][2] = -1e30f;
                if (col + 1 > rB) s[nt][3] = -1e30f;
            }
        }

        // ---- Online softmax (rows gid and gid+8), log2 domain ----
        float mx0 = -1e30f, mx1 = -1e30f;
#pragma unroll
        for (int nt = 0; nt < 8; nt++) {
            mx0 = fmaxf(mx0, fmaxf(s[nt][0], s[nt][1]));
            mx1 = fmaxf(mx1, fmaxf(s[nt][2], s[nt][3]));
        }
        mx0 = fmaxf(mx0, __shfl_xor_sync(0xffffffffu, mx0, 1));
        mx0 = fmaxf(mx0, __shfl_xor_sync(0xffffffffu, mx0, 2));
        mx1 = fmaxf(mx1, __shfl_xor_sync(0xffffffffu, mx1, 1));
        mx1 = fmaxf(mx1, __shfl_xor_sync(0xffffffffu, mx1, 2));
        float mn0 = fmaxf(mrow0, mx0), mn1 = fmaxf(mrow1, mx1);
        float al0 = exp2f(mrow0 - mn0), al1 = exp2f(mrow1 - mn1);

        float rs0 = 0.0f, rs1 = 0.0f;
#pragma unroll
        for (int nt = 0; nt < 8; nt++) {
            s[nt][0] = exp2f(s[nt][0] - mn0);
            s[nt][1] = exp2f(s[nt][1] - mn0);
            s[nt][2] = exp2f(s[nt][2] - mn1);
            s[nt][3] = exp2f(s[nt][3] - mn1);
            rs0 += s[nt][0] + s[nt][1];
            rs1 += s[nt][2] + s[nt][3];
        }
        rs0 += __shfl_xor_sync(0xffffffffu, rs0, 1);
        rs0 += __shfl_xor_sync(0xffffffffu, rs0, 2);
        rs1 += __shfl_xor_sync(0xffffffffu, rs1, 1);
        rs1 += __shfl_xor_sync(0xffffffffu, rs1, 2);
        lrow0 = lrow0 * al0 + rs0;
        lrow1 = lrow1 * al1 + rs1;
        mrow0 = mn0;
        mrow1 = mn1;

#pragma unroll
        for (int nt = 0; nt < 8; nt++) {
            o[nt][0] *= al0; o[nt][1] *= al0;
            o[nt][2] *= al1; o[nt][3] *= al1;
        }

        // ---- O += P V: P C-frags repacked to A-frags (hi/lo), V from smem ----
#pragma unroll
        for (int kk = 0; kk < 4; kk++) {
            const int ja = 2 * kk, jc = 2 * kk + 1;
            u32 pah[4], pal[4];
            pah[0] = cvt_bf2(s[ja][0], s[ja][1]);
            pah[1] = cvt_bf2(s[ja][2], s[ja][3]);
            pah[2] = cvt_bf2(s[jc][0], s[jc][1]);
            pah[3] = cvt_bf2(s[jc][2], s[jc][3]);
            {
                float2 f0 = bf2_to_f2(pah[0]);
                float2 f1 = bf2_to_f2(pah[1]);
                float2 f2 = bf2_to_f2(pah[2]);
                float2 f3 = bf2_to_f2(pah[3]);
                pal[0] = cvt_bf2(s[ja][0] - f0.x, s[ja][1] - f0.y);
                pal[1] = cvt_bf2(s[ja][2] - f1.x, s[ja][3] - f1.y);
                pal[2] = cvt_bf2(s[jc][0] - f2.x, s[jc][1] - f2.y);
                pal[3] = cvt_bf2(s[jc][2] - f3.x, s[jc][3] - f3.y);
            }
#pragma unroll
            for (int nt = 0; nt < 8; nt++) {
                u32 vh[2], vl[2];
                u32 rb = (nt * 8 + brow) * (PITCH * 2) + (kk * 16 + bcol8) * 2;
                ldm_x2(vh[0], vh[1], sb + VH_OFF + rb);
                ldm_x2(vl[0], vl[1], sb + VL_OFF + rb);
                mma_bf16(o[nt], pah, vh);
                mma_bf16(o[nt], pah, vl);
                mma_bf16(o[nt], pal, vh);
            }
        }
        __syncthreads();
    }

    // ---- Write unnormalized partial O + stats ----
#pragma unroll
    for (int nt = 0; nt < 8; nt++) {
        int n = nt * 8 + 2 * tig;
        *(float2*)&Op[(size_t)(m0 + wm + gid) * HDIM + n]     = make_float2(o[nt][0], o[nt][1]);
        *(float2*)&Op[(size_t)(m0 + wm + gid + 8) * HDIM + n] = make_float2(o[nt][2], o[nt][3]);
    }
    if (tig == 0) {
        g_stats[split * MTOT + m0 + wm + gid]     = make_float2(mrow0, lrow0);
        g_stats[split * MTOT + m0 + wm + gid + 8] = make_float2(mrow1, lrow1);
    }
}

// ---------------------------------------------------------------------------
// Merge split partials (stats are in log2 domain -> exp2f).
// ---------------------------------------------------------------------------
__global__ __launch_bounds__(256) void merge_kernel(float* __restrict__ out)
{
    int idx = blockIdx.x * 256 + threadIdx.x;
    int m = idx >> 4;
    int h = (idx & 15) * 4;

    float2 s0 = g_stats[m];
    float2 s1 = g_stats[MTOT + m];
    float mm = fmaxf(s0.x, s1.x);
    float a0 = exp2f(s0.x - mm);
    float a1 = exp2f(s1.x - mm);
    float rinv = 1.0f / (s0.y * a0 + s1.y * a1);

    float4 o0 = *(const float4*)&g_Opart[(size_t)m * HDIM + h];
    float4 o1 = *(const float4*)&g_Opart[(size_t)(MTOT + m) * HDIM + h];

    float4 r;
    r.x = (o0.x * a0 + o1.x * a1) * rinv;
    r.y = (o0.y * a0 + o1.y * a1) * rinv;
    r.z = (o0.z * a0 + o1.z * a1) * rinv;
    r.w = (o0.w * a0 + o1.w * a1) * rinv;
    *(float4*)&out[(size_t)m * HDIM + h] = r;
}

// ---------------------------------------------------------------------------
extern "C" void kernel_launch(void* const* d_in, const int* in_sizes, int n_in,
                              void* d_out, int out_size)
{
    const float* x  = (const float*)d_in[0];
    const float* Wk = (const float*)d_in[2];
    const float* Wq = (const float*)d_in[3];
    const float* Wv = (const float*)d_in[4];
    float* out = (float*)d_out;

    wconv_kernel<<<3 * HDIM * CDIM / 256, 256>>>(Wk, Wq, Wv);

    cudaFuncSetAttribute(proj_tc_kernel,
                         cudaFuncAttributeMaxDynamicSharedMemorySize, PROJ_SMEM);
    dim3 gp(128, 3);
    proj_tc_kernel<<<gp, 256, PROJ_SMEM>>>(x);

    cudaFuncSetAttribute(attn_tc_kernel,
                         cudaFuncAttributeMaxDynamicSharedMemorySize, ATTN_SMEM);
    dim3 ga(64 * NSPLIT, 4);
    attn_tc_kernel<<<ga, 128, ATTN_SMEM>>>();

    merge_kernel<<<(MTOT * 16) / 256, 256>>>(out);
}

// round 13
// speedup vs baseline: 2.7873x; 1.2185x over previous
#include <cuda_runtime.h>
#include <cuda_bf16.h>
#include <math.h>
#include <stdint.h>

#define BSZ  4
#define TLEN 4096
#define CDIM 1024
#define HDIM 64
#define MTOT (BSZ * TLEN)
#define NSPLIT 2

// Projected operands, bf16 hi/lo split.
// Q (pre-scaled by 0.125*log2(e)) and K: [m][h] row-major. Vt: [h][m] (transposed).
__device__ __nv_bfloat16 g_Qhi[MTOT * HDIM], g_Qlo[MTOT * HDIM];
__device__ __nv_bfloat16 g_Khi[MTOT * HDIM], g_Klo[MTOT * HDIM];
__device__ __nv_bfloat16 g_Vthi[HDIM * MTOT], g_Vtlo[HDIM * MTOT];
// Split-KV partials.
__device__ float  g_Opart[NSPLIT * MTOT * HDIM];
__device__ float2 g_stats[NSPLIT * MTOT];
// Weights pre-split to bf16 hi/lo, [which][h][c], which: 0=Q, 1=K, 2=V.
__device__ __nv_bfloat16 g_Whi[3 * HDIM * CDIM];
__device__ __nv_bfloat16 g_Wlo[3 * HDIM * CDIM];

typedef unsigned long long u64;
typedef unsigned int u32;

// ---------------- mma.sync helpers ----------------
__device__ __forceinline__ u32 smem_u32(const void* p) {
    u32 a;
    asm("{ .reg .u64 t; cvta.to.shared.u64 t, %1; cvt.u32.u64 %0, t; }"
        : "=r"(a) : "l"(p));
    return a;
}
__device__ __forceinline__ void ldm_x4(u32 &r0, u32 &r1, u32 &r2, u32 &r3, u32 addr) {
    asm volatile("ldmatrix.sync.aligned.m8n8.x4.shared.b16 {%0,%1,%2,%3}, [%4];"
                 : "=r"(r0), "=r"(r1), "=r"(r2), "=r"(r3) : "r"(addr));
}
__device__ __forceinline__ void mma_bf16(float* d, const u32* a, const u32* b) {
    asm volatile(
        "mma.sync.aligned.m16n8k16.row.col.f32.bf16.bf16.f32 "
        "{%0,%1,%2,%3}, {%4,%5,%6,%7}, {%8,%9}, {%0,%1,%2,%3};"
        : "+f"(d[0]), "+f"(d[1]), "+f"(d[2]), "+f"(d[3])
        : "r"(a[0]), "r"(a[1]), "r"(a[2]), "r"(a[3]), "r"(b[0]), "r"(b[1]));
}
__device__ __forceinline__ u64 pack32(u32 a, u32 b) {
    u64 r; asm("mov.b64 %0, {%1, %2};" : "=l"(r) : "r"(a), "r"(b)); return r;
}
__device__ __forceinline__ u32 cvt_bf2(float a, float b) {
    __nv_bfloat162 h = __floats2bfloat162_rn(a, b);
    return *(u32*)&h;
}
__device__ __forceinline__ float2 bf2_to_f2(u32 v) {
    __nv_bfloat162 h = *(__nv_bfloat162*)&v;
    return __bfloat1622float2(h);
}
// float4 -> 4 bf16 hi + 4 bf16 lo, packed u64s
__device__ __forceinline__ void cvt_hilo(float4 v, u64 &hi, u64 &lo) {
    u32 h01 = cvt_bf2(v.x, v.y), h23 = cvt_bf2(v.z, v.w);
    float2 f01 = bf2_to_f2(h01), f23 = bf2_to_f2(h23);
    u32 l01 = cvt_bf2(v.x - f01.x, v.y - f01.y);
    u32 l23 = cvt_bf2(v.z - f23.x, v.w - f23.y);
    hi = pack32(h01, h23);
    lo = pack32(l01, l23);
}

// ---------------------------------------------------------------------------
// Weight pre-split: fp32 -> bf16 hi/lo. which: 0=Wq, 1=Wk, 2=Wv.
// ---------------------------------------------------------------------------
__global__ __launch_bounds__(256) void wconv_kernel(
    const float* __restrict__ Wk,
    const float* __restrict__ Wq,
    const float* __restrict__ Wv)
{
    int idx = blockIdx.x * 256 + threadIdx.x;     // 3 * 65536
    int w = idx >> 16;
    int r = idx & 0xFFFF;
    const float* src = (w == 0) ? Wq : (w == 1) ? Wk : Wv;
    float v = src[r];
    __nv_bfloat16 hi = __float2bfloat16(v);
    __nv_bfloat16 lo = __float2bfloat16(v - __bfloat162float(hi));
    g_Whi[idx] = hi;
    g_Wlo[idx] = lo;
}

// ---------------------------------------------------------------------------
// FUSED tensor-core projection: one CTA computes Q, K, V for its 128 rows.
// X loaded + converted ONCE; A fragments reused across all 3 weights.
// 128 CTAs x 256 threads (8 warps: wm 4x32, wn 2x32).
// ---------------------------------------------------------------------------
#define PITCH 72
#define PS_AHI 0
#define PS_ALO (128 * PITCH * 2)                  // 18432
#define PS_B   (2 * 128 * PITCH * 2)              // 36864; tile t = w*2+half, 9216 B each
#define PROJ_SMEM (PS_B + 6 * 64 * PITCH * 2)     // 92160

__global__ __launch_bounds__(256) void proj_tc_kernel(const float* __restrict__ x)
{
    extern __shared__ char psm[];
    const u32 sb = smem_u32(psm);

    const int m0    = blockIdx.x * 128;
    const int tid   = threadIdx.x;
    const int lane  = tid & 31;
    const int wid   = tid >> 5;
    const int wm    = (wid & 3) * 32;
    const int wn    = (wid >> 2) * 32;

    float acc[3][2][4][4];
#pragma unroll
    for (int w = 0; w < 3; w++)
#pragma unroll
        for (int mt = 0; mt < 2; mt++)
#pragma unroll
            for (int nt = 0; nt < 4; nt++)
#pragma unroll
                for (int c = 0; c < 4; c++) acc[w][mt][nt][c] = 0.0f;

    const int arow  = (lane & 15);
    const int acol8 = (lane >> 4) << 3;
    const int brow4 = ((lane >> 4) << 3) | (lane & 7);   // x4 B: row within nt-pair
    const int bcol4 = ((lane >> 3) & 1) << 3;

#pragma unroll 1
    for (int chunk = 0; chunk < 16; chunk++) {
        const int kc = chunk * 64;

        // X chunk [128 x 64] f32 -> bf16 hi/lo smem (once for all 3 weights)
#pragma unroll
        for (int i = 0; i < 8; i++) {
            int idx = tid + i * 256;
            int row = idx >> 4;
            int cg  = idx & 15;
            float4 v = *(const float4*)(x + (size_t)(m0 + row) * CDIM + kc + cg * 4);
            u64 hi, lo;
            cvt_hilo(v, hi, lo);
            *(u64*)(psm + PS_AHI + row * (PITCH * 2) + cg * 8) = hi;
            *(u64*)(psm + PS_ALO + row * (PITCH * 2) + cg * 8) = lo;
        }
        // W chunks: 6 tiles (3 weights x hi/lo), 6144 u64 items
#pragma unroll
        for (int i = 0; i < 24; i++) {
            int idx  = tid + i * 256;
            int t    = idx >> 10;                 // 0..5
            int rem  = idx & 1023;
            int row  = rem >> 4;
            int cg   = rem & 15;
            const __nv_bfloat16* src = (t & 1) ? g_Wlo : g_Whi;
            u64 v = *(const u64*)(src + (size_t)(t >> 1) * (HDIM * CDIM)
                                  + (size_t)row * CDIM + kc + cg * 4);
            *(u64*)(psm + PS_B + t * 9216 + row * (PITCH * 2) + cg * 8) = v;
        }
        __syncthreads();

#pragma unroll
        for (int ks = 0; ks < 4; ks++) {
            const int kb = ks * 16;
            u32 ah[2][4], al[2][4];
#pragma unroll
            for (int mt = 0; mt < 2; mt++) {
                u32 ra = (wm + mt * 16 + arow) * (PITCH * 2) + (kb + acol8) * 2;
                ldm_x4(ah[mt][0], ah[mt][1], ah[mt][2], ah[mt][3], sb + PS_AHI + ra);
                ldm_x4(al[mt][0], al[mt][1], al[mt][2], al[mt][3], sb + PS_ALO + ra);
            }
#pragma unroll
            for (int w = 0; w < 3; w++) {
                u32 bh[4][2], bl[4][2];
#pragma unroll
                for (int ntp = 0; ntp < 2; ntp++) {
                    u32 rb = (wn + ntp * 16 + brow4) * (PITCH * 2) + (kb + bcol4) * 2;
                    ldm_x4(bh[2 * ntp][0], bh[2 * ntp][1], bh[2 * ntp + 1][0],
                           bh[2 * ntp + 1][1], sb + PS_B + (2 * w) * 9216 + rb);
                    ldm_x4(bl[2 * ntp][0], bl[2 * ntp][1], bl[2 * ntp + 1][0],
                           bl[2 * ntp + 1][1], sb + PS_B + (2 * w + 1) * 9216 + rb);
                }
#pragma unroll
                for (int mt = 0; mt < 2; mt++)
#pragma unroll
                    for (int nt = 0; nt < 4; nt++) {
                        mma_bf16(acc[w][mt][nt], ah[mt], bh[nt]);
                        mma_bf16(acc[w][mt][nt], ah[mt], bl[nt]);
                        mma_bf16(acc[w][mt][nt], al[mt], bh[nt]);
                    }
            }
        }
        __syncthreads();
    }

    // Epilogue -> bf16 hi/lo operand arrays.
    const int gid = lane >> 2;
    const int tig = lane & 3;
    const float qsc = 0.18033688011112042f;   // H^-0.5 * log2(e)

#pragma unroll
    for (int w = 0; w < 3; w++)
#pragma unroll
        for (int mt = 0; mt < 2; mt++)
#pragma unroll
            for (int nt = 0; nt < 4; nt++) {
                int m = m0 + wm + mt * 16 + gid;
                int n = wn + nt * 8 + 2 * tig;
                float sc = (w == 0) ? qsc : 1.0f;
                float v0 = acc[w][mt][nt][0] * sc;
                float v1 = acc[w][mt][nt][1] * sc;
                float v2 = acc[w][mt][nt][2] * sc;
                float v3 = acc[w][mt][nt][3] * sc;

                if (w == 2) {
                    __nv_bfloat16 h0 = __float2bfloat16(v0);
                    __nv_bfloat16 h1 = __float2bfloat16(v1);
                    __nv_bfloat16 h2 = __float2bfloat16(v2);
                    __nv_bfloat16 h3 = __float2bfloat16(v3);
                    g_Vthi[(size_t)n * MTOT + m]           = h0;
                    g_Vthi[(size_t)(n + 1) * MTOT + m]     = h1;
                    g_Vthi[(size_t)n * MTOT + m + 8]       = h2;
                    g_Vthi[(size_t)(n + 1) * MTOT + m + 8] = h3;
                    g_Vtlo[(size_t)n * MTOT + m]           = __float2bfloat16(v0 - __bfloat162float(h0));
                    g_Vtlo[(size_t)(n + 1) * MTOT + m]     = __float2bfloat16(v1 - __bfloat162float(h1));
                    g_Vtlo[(size_t)n * MTOT + m + 8]       = __float2bfloat16(v2 - __bfloat162float(h2));
                    g_Vtlo[(size_t)(n + 1) * MTOT + m + 8] = __float2bfloat16(v3 - __bfloat162float(h3));
                } else {
                    __nv_bfloat16* Ahi = (w == 0) ? g_Qhi : g_Khi;
                    __nv_bfloat16* Alo = (w == 0) ? g_Qlo : g_Klo;
                    u32 h01 = cvt_bf2(v0, v1);
                    float2 f01 = bf2_to_f2(h01);
                    u32 l01 = cvt_bf2(v0 - f01.x, v1 - f01.y);
                    u32 h23 = cvt_bf2(v2, v3);
                    float2 f23 = bf2_to_f2(h23);
                    u32 l23 = cvt_bf2(v2 - f23.x, v3 - f23.y);
                    *(u32*)&Ahi[(size_t)m * HDIM + n]       = h01;
                    *(u32*)&Alo[(size_t)m * HDIM + n]       = l01;
                    *(u32*)&Ahi[(size_t)(m + 8) * HDIM + n] = h23;
                    *(u32*)&Alo[(size_t)(m + 8) * HDIM + n] = l23;
                }
            }
}

// ---------------------------------------------------------------------------
// FA2-style tensor-core causal flash attention, split-KV (R11-proven),
// with ldmatrix.x4 B-fragments (half the ldmatrix count).
// ---------------------------------------------------------------------------
#define QH_OFF 0
#define QL_OFF 9216
#define KH_OFF 18432
#define KL_OFF 27648
#define VH_OFF 36864
#define VL_OFF 46080
#define ATTN_SMEM 55296

__global__ __launch_bounds__(128) void attn_tc_kernel()
{
    extern __shared__ char csm[];
    const u32 sb = smem_u32(csm);

    const int b     = blockIdx.y;
    const int qb    = 63 - (blockIdx.x >> 1);   // longest CTAs first
    const int split = blockIdx.x & 1;
    const int nblk  = qb + 1;
    const int j0    = (nblk * split) >> 1;
    const int j1    = (nblk * (split + 1)) >> 1;

    const int tid  = threadIdx.x;
    const int wid  = tid >> 5;
    const int lane = tid & 31;
    const int gid  = lane >> 2;
    const int tig  = lane & 3;
    const int wm   = wid * 16;
    const int m0   = b * TLEN + qb * 64;

    float* Op = g_Opart + (size_t)split * MTOT * HDIM;

    if (j0 == j1) {   // empty split: neutral partials
#pragma unroll
        for (int nt = 0; nt < 8; nt++) {
            int n = nt * 8 + 2 * tig;
            *(float2*)&Op[(size_t)(m0 + wm + gid) * HDIM + n]     = make_float2(0.f, 0.f);
            *(float2*)&Op[(size_t)(m0 + wm + gid + 8) * HDIM + n] = make_float2(0.f, 0.f);
        }
        if (tig == 0) {
            g_stats[split * MTOT + m0 + wm + gid]     = make_float2(-1e30f, 0.f);
            g_stats[split * MTOT + m0 + wm + gid + 8] = make_float2(-1e30f, 0.f);
        }
        return;
    }

    // ---- Load Q tile (64 x 64 bf16 hi/lo) into smem ----
#pragma unroll
    for (int i = 0; i < 16; i++) {
        int idx  = tid + i * 128;
        int half = idx >> 10;
        int rem  = idx & 1023;
        int row  = rem >> 4;
        int cg   = rem & 15;
        const __nv_bfloat16* src = half ? g_Qlo : g_Qhi;
        u64 v = *(const u64*)(src + (size_t)(m0 + row) * HDIM + cg * 4);
        *(u64*)(csm + (half ? QL_OFF : QH_OFF) + row * (PITCH * 2) + cg * 8) = v;
    }
    __syncthreads();

    const int arow  = (lane & 15);
    const int acol8 = (lane >> 4) << 3;
    const int brow4 = ((lane >> 4) << 3) | (lane & 7);
    const int bcol4 = ((lane >> 3) & 1) << 3;

    u32 qh[4][4], ql[4][4];
#pragma unroll
    for (int kk = 0; kk < 4; kk++) {
        u32 ra = (wm + arow) * (PITCH * 2) + (kk * 16 + acol8) * 2;
        ldm_x4(qh[kk][0], qh[kk][1], qh[kk][2], qh[kk][3], sb + QH_OFF + ra);
        ldm_x4(ql[kk][0], ql[kk][1], ql[kk][2], ql[kk][3], sb + QL_OFF + ra);
    }

    float o[8][4];
#pragma unroll
    for (int nt = 0; nt < 8; nt++)
#pragma unroll
        for (int c = 0; c < 4; c++) o[nt][c] = 0.0f;
    float mrow0 = -1e30f, mrow1 = -1e30f, lrow0 = 0.0f, lrow1 = 0.0f;

    for (int jb = j0; jb < j1; jb++) {
        const int kb = b * TLEN + jb * 64;

        // Load K [key][h] and Vt [h][key] hi/lo tiles
#pragma unroll
        for (int i = 0; i < 16; i++) {
            int idx  = tid + i * 128;
            int half = idx >> 10;
            int rem  = idx & 1023;
            int row  = rem >> 4;
            int cg   = rem & 15;
            const __nv_bfloat16* src = half ? g_Klo : g_Khi;
            u64 v = *(const u64*)(src + (size_t)(kb + row) * HDIM + cg * 4);
            *(u64*)(csm + (half ? KL_OFF : KH_OFF) + row * (PITCH * 2) + cg * 8) = v;
        }
#pragma unroll
        for (int i = 0; i < 16; i++) {
            int idx  = tid + i * 128;
            int half = idx >> 10;
            int rem  = idx & 1023;
            int row  = rem >> 4;      // h
            int cg   = rem & 15;      // key chunk
            const __nv_bfloat16* src = half ? g_Vtlo : g_Vthi;
            u64 v = *(const u64*)(src + (size_t)row * MTOT + kb + cg * 4);
            *(u64*)(csm + (half ? VL_OFF : VH_OFF) + row * (PITCH * 2) + cg * 8) = v;
        }
        __syncthreads();

        // ---- S = Q K^T (log2 domain), 16 x 64 per warp ----
        float s[8][4];
#pragma unroll
        for (int nt = 0; nt < 8; nt++)
#pragma unroll
            for (int c = 0; c < 4; c++) s[nt][c] = 0.0f;

#pragma unroll
        for (int kk = 0; kk < 4; kk++) {
#pragma unroll
            for (int ntp = 0; ntp < 4; ntp++) {
                u32 rb = (ntp * 16 + brow4) * (PITCH * 2) + (kk * 16 + bcol4) * 2;
                u32 bh[2][2], bl[2][2];
                ldm_x4(bh[0][0], bh[0][1], bh[1][0], bh[1][1], sb + KH_OFF + rb);
                ldm_x4(bl[0][0], bl[0][1], bl[1][0], bl[1][1], sb + KL_OFF + rb);
                mma_bf16(s[2 * ntp],     qh[kk], bh[0]);
                mma_bf16(s[2 * ntp],     qh[kk], bl[0]);
                mma_bf16(s[2 * ntp],     ql[kk], bh[0]);
                mma_bf16(s[2 * ntp + 1], qh[kk], bh[1]);
                mma_bf16(s[2 * ntp + 1], qh[kk], bl[1]);
                mma_bf16(s[2 * ntp + 1], ql[kk], bh[1]);
            }
        }

        // ---- Causal mask (diagonal block only) ----
        if (jb == qb) {
#pragma unroll
            for (int nt = 0; nt < 8; nt++) {
                int col = nt * 8 + 2 * tig;
                int rA = wm + gid, rB = wm + gid + 8;
                if (col > rA)     s[nt][0] = -1e30f;
                if (col + 1 > rA) s[nt][1] = -1e30f;
                if (col > rB)     s[nt][2] = -1e30f;
                if (col + 1 > rB) s[nt][3] = -1e30f;
            }
        }

        // ---- Online softmax (rows gid and gid+8), log2 domain ----
        float mx0 = -1e30f, mx1 = -1e30f;
#pragma unroll
        for (int nt = 0; nt < 8; nt++) {
            mx0 = fmaxf(mx0, fmaxf(s[nt][0], s[nt][1]));
            mx1 = fmaxf(mx1, fmaxf(s[nt][2], s[nt][3]));
        }
        mx0 = fmaxf(mx0, __shfl_xor_sync(0xffffffffu, mx0, 1));
        mx0 = fmaxf(mx0, __shfl_xor_sync(0xffffffffu, mx0, 2));
        mx1 = fmaxf(mx1, __shfl_xor_sync(0xffffffffu, mx1, 1));
        mx1 = fmaxf(mx1, __shfl_xor_sync(0xffffffffu, mx1, 2));
        float mn0 = fmaxf(mrow0, mx0), mn1 = fmaxf(mrow1, mx1);
        float al0 = exp2f(mrow0 - mn0), al1 = exp2f(mrow1 - mn1);

        float rs0 = 0.0f, rs1 = 0.0f;
#pragma unroll
        for (int nt = 0; nt < 8; nt++) {
            s[nt][0] = exp2f(s[nt][0] - mn0);
            s[nt][1] = exp2f(s[nt][1] - mn0);
            s[nt][2] = exp2f(s[nt][2] - mn1);
            s[nt][3] = exp2f(s[nt][3] - mn1);
            rs0 += s[nt][0] + s[nt][1];
            rs1 += s[nt][2] + s[nt][3];
        }
        rs0 += __shfl_xor_sync(0xffffffffu, rs0, 1);
        rs0 += __shfl_xor_sync(0xffffffffu, rs0, 2);
        rs1 += __shfl_xor_sync(0xffffffffu, rs1, 1);
        rs1 += __shfl_xor_sync(0xffffffffu, rs1, 2);
        lrow0 = lrow0 * al0 + rs0;
        lrow1 = lrow1 * al1 + rs1;
        mrow0 = mn0;
        mrow1 = mn1;

#pragma unroll
        for (int nt = 0; nt < 8; nt++) {
            o[nt][0] *= al0; o[nt][1] *= al0;
            o[nt][2] *= al1; o[nt][3] *= al1;
        }

        // ---- O += P V: P C-frags repacked to A-frags (hi/lo), V via x4 ----
#pragma unroll
        for (int kk = 0; kk < 4; kk++) {
            const int ja = 2 * kk, jc = 2 * kk + 1;
            u32 pah[4], pal[4];
            pah[0] = cvt_bf2(s[ja][0], s[ja][1]);
            pah[1] = cvt_bf2(s[ja][2], s[ja][3]);
            pah[2] = cvt_bf2(s[jc][0], s[jc][1]);
            pah[3] = cvt_bf2(s[jc][2], s[jc][3]);
            {
                float2 f0 = bf2_to_f2(pah[0]);
                float2 f1 = bf2_to_f2(pah[1]);
                float2 f2 = bf2_to_f2(pah[2]);
                float2 f3 = bf2_to_f2(pah[3]);
                pal[0] = cvt_bf2(s[ja][0] - f0.x, s[ja][1] - f0.y);
                pal[1] = cvt_bf2(s[ja][2] - f1.x, s[ja][3] - f1.y);
                pal[2] = cvt_bf2(s[jc][0] - f2.x, s[jc][1] - f2.y);
                pal[3] = cvt_bf2(s[jc][2] - f3.x, s[jc][3] - f3.y);
            }
#pragma unroll
            for (int ntp = 0; ntp < 4; ntp++) {
                u32 rb = (ntp * 16 + brow4) * (PITCH * 2) + (kk * 16 + bcol4) * 2;
                u32 vh[2][2], vl[2][2];
                ldm_x4(vh[0][0], vh[0][1], vh[1][0], vh[1][1], sb + VH_OFF + rb);
                ldm_x4(vl[0][0], vl[0][1], vl[1][0], vl[1][1], sb + VL_OFF + rb);
                mma_bf16(o[2 * ntp],     pah, vh[0]);
                mma_bf16(o[2 * ntp],     pah, vl[0]);
                mma_bf16(o[2 * ntp],     pal, vh[0]);
                mma_bf16(o[2 * ntp + 1], pah, vh[1]);
                mma_bf16(o[2 * ntp + 1], pah, vl[1]);
                mma_bf16(o[2 * ntp + 1], pal, vh[1]);
            }
        }
        __syncthreads();
    }

    // ---- Write unnormalized partial O + stats ----
#pragma unroll
    for (int nt = 0; nt < 8; nt++) {
        int n = nt * 8 + 2 * tig;
        *(float2*)&Op[(size_t)(m0 + wm + gid) * HDIM + n]     = make_float2(o[nt][0], o[nt][1]);
        *(float2*)&Op[(size_t)(m0 + wm + gid + 8) * HDIM + n] = make_float2(o[nt][2], o[nt][3]);
    }
    if (tig == 0) {
        g_stats[split * MTOT + m0 + wm + gid]     = make_float2(mrow0, lrow0);
        g_stats[split * MTOT + m0 + wm + gid + 8] = make_float2(mrow1, lrow1);
    }
}

// ---------------------------------------------------------------------------
// Merge split partials (stats are in log2 domain -> exp2f).
// ---------------------------------------------------------------------------
__global__ __launch_bounds__(256) void merge_kernel(float* __restrict__ out)
{
    int idx = blockIdx.x * 256 + threadIdx.x;
    int m = idx >> 4;
    int h = (idx & 15) * 4;

    float2 s0 = g_stats[m];
    float2 s1 = g_stats[MTOT + m];
    float mm = fmaxf(s0.x, s1.x);
    float a0 = exp2f(s0.x - mm);
    float a1 = exp2f(s1.x - mm);
    float rinv = 1.0f / (s0.y * a0 + s1.y * a1);

    float4 o0 = *(const float4*)&g_Opart[(size_t)m * HDIM + h];
    float4 o1 = *(const float4*)&g_Opart[(size_t)(MTOT + m) * HDIM + h];

    float4 r;
    r.x = (o0.x * a0 + o1.x * a1) * rinv;
    r.y = (o0.y * a0 + o1.y * a1) * rinv;
    r.z = (o0.z * a0 + o1.z * a1) * rinv;
    r.w = (o0.w * a0 + o1.w * a1) * rinv;
    *(float4*)&out[(size_t)m * HDIM + h] = r;
}

// ---------------------------------------------------------------------------
extern "C" void kernel_launch(void* const* d_in, const int* in_sizes, int n_in,
                              void* d_out, int out_size)
{
    const float* x  = (const float*)d_in[0];
    const float* Wk = (const float*)d_in[2];
    const float* Wq = (const float*)d_in[3];
    const float* Wv = (const float*)d_in[4];
    float* out = (float*)d_out;

    wconv_kernel<<<3 * HDIM * CDIM / 256, 256>>>(Wk, Wq, Wv);

    cudaFuncSetAttribute(proj_tc_kernel,
                         cudaFuncAttributeMaxDynamicSharedMemorySize, PROJ_SMEM);
    proj_tc_kernel<<<128, 256, PROJ_SMEM>>>(x);

    cudaFuncSetAttribute(attn_tc_kernel,
                         cudaFuncAttributeMaxDynamicSharedMemorySize, ATTN_SMEM);
    dim3 ga(64 * NSPLIT, 4);
    attn_tc_kernel<<<ga, 128, ATTN_SMEM>>>();

    merge_kernel<<<(MTOT * 16) / 256, 256>>>(out);
}